// round 1
// baseline (speedup 1.0000x reference)
#include <cuda_runtime.h>
#include <math.h>

#define S 1024
#define D 1024
#define H 16
#define HD 64
#define NL 6
#define DFF 4096
#define EPS 1.1920929e-07f

// ---------------- scratch (device globals; no allocation) ----------------
__device__ float g_x [S * D];
__device__ float g_x0[S * D];
__device__ float g_xl[S * D];
__device__ float g_xn[S * D];
__device__ float g_q [S * D];
__device__ float g_k [S * D];
__device__ float g_v [S * D];
__device__ float g_v1[S * D];
__device__ float g_y [S * D];
__device__ float g_h [S * DFF];
__device__ float g_p [(size_t)H * S * S];
__device__ int   g_cpad[S + 1];
__device__ unsigned char g_mask[(size_t)S * S];

// ---------------- small kernels ----------------

__global__ void build_prefix_k(const int* __restrict__ levels, int* __restrict__ cpad) {
    if (threadIdx.x == 0) {
        cpad[0] = 0;
        for (int i = 0; i < S; i++) cpad[i + 1] = cpad[i] + (levels[i] == 0 ? 1 : 0);
    }
}

__global__ void build_mask_k(const int* __restrict__ levels, const int* __restrict__ sample,
                             const int* __restrict__ cpad, unsigned char* __restrict__ mask) {
    int idx = blockIdx.x * blockDim.x + threadIdx.x;
    int q = idx >> 10;
    int k = idx & 1023;
    bool causal = q >= k;
    bool same = sample[q] == sample[k];
    int cnt = cpad[q] - cpad[k + 1];
    bool markov = (levels[k] == 0) && (cnt > 0);
    mask[idx] = (causal && same && !markov) ? 1 : 0;
}

// RMS over rows of length L (L multiple of 256)
__global__ void rms_rows_k(const float* __restrict__ in, float* __restrict__ out, int L) {
    int row = blockIdx.x;
    const float* p = in + (size_t)row * L;
    float* o = out + (size_t)row * L;
    int tid = threadIdx.x;
    float ss = 0.f;
    for (int i = tid; i < L; i += 256) { float t = p[i]; ss += t * t; }
    __shared__ float red[256];
    red[tid] = ss;
    __syncthreads();
    for (int s = 128; s > 0; s >>= 1) {
        if (tid < s) red[tid] += red[tid + s];
        __syncthreads();
    }
    float scale = rsqrtf(red[0] / (float)L + EPS);
    for (int i = tid; i < L; i += 256) o[i] = p[i] * scale;
}

// per-(s,h) RMS over 64 elems; one warp per row; rows contiguous (S*H rows of 64)
__global__ void rms_head_k(float* __restrict__ t) {
    int warp = (blockIdx.x * blockDim.x + threadIdx.x) >> 5;
    int lane = threadIdx.x & 31;
    float* p = t + (size_t)warp * 64;
    float a = p[lane], b = p[lane + 32];
    float ss = a * a + b * b;
    #pragma unroll
    for (int o = 16; o; o >>= 1) ss += __shfl_xor_sync(0xFFFFFFFFu, ss, o);
    float sc = rsqrtf(ss / 64.f + EPS);
    p[lane] = a * sc;
    p[lane + 32] = b * sc;
}

__global__ void rope_k(float* __restrict__ t) {
    int idx = blockIdx.x * blockDim.x + threadIdx.x;  // S*H*32
    int j = idx & 31;
    int h = (idx >> 5) & 15;
    int s = idx >> 9;
    float inv = powf(10000.f, -((float)(2 * j)) / 64.f);
    float fr = (float)s * inv;
    float c = cosf(fr), sn = sinf(fr);
    float* base = t + (size_t)s * D + h * HD;
    float x1 = base[j], x2 = base[j + 32];
    base[j]      = x1 * c + x2 * sn;
    base[j + 32] = -x1 * sn + x2 * c;
}

__global__ void copy_k(const float* __restrict__ in, float* __restrict__ out) {
    int i = blockIdx.x * blockDim.x + threadIdx.x;
    out[i] = in[i];
}

__global__ void xl_k(const float* __restrict__ x, const float* __restrict__ x0,
                     const float* __restrict__ lambdas, int layer, float* __restrict__ xl) {
    int i = blockIdx.x * blockDim.x + threadIdx.x;
    float l0 = lambdas[layer * 2 + 0];
    float l1 = lambdas[layer * 2 + 1];
    xl[i] = l0 * x[i] + l1 * x0[i];
}

__global__ void vmix_k(float* __restrict__ v, const float* __restrict__ v1,
                       const float* __restrict__ lamb, int layer) {
    int i = blockIdx.x * blockDim.x + threadIdx.x;
    float la = lamb[layer];
    v[i] = (1.f - la) * v[i] + la * v1[i];
}

// masked softmax over row of S, in-place on scores; scale folded in here
__global__ void softmax_k(float* __restrict__ p, const unsigned char* __restrict__ mask,
                          float scale) {
    int qi = blockIdx.x;
    int h = blockIdx.y;
    float* row = p + ((size_t)h * S + qi) * S;
    const unsigned char* m = mask + (size_t)qi * S;
    int tid = threadIdx.x;
    float vals[4];
    float mx = -1e30f;
    #pragma unroll
    for (int j = 0; j < 4; j++) {
        int k = tid + (j << 8);
        float v = m[k] ? row[k] * scale : -1e30f;
        vals[j] = v;
        mx = fmaxf(mx, v);
    }
    __shared__ float red[256];
    red[tid] = mx;
    __syncthreads();
    for (int s = 128; s > 0; s >>= 1) {
        if (tid < s) red[tid] = fmaxf(red[tid], red[tid + s]);
        __syncthreads();
    }
    mx = red[0];
    __syncthreads();
    float sum = 0.f;
    #pragma unroll
    for (int j = 0; j < 4; j++) { vals[j] = expf(vals[j] - mx); sum += vals[j]; }
    red[tid] = sum;
    __syncthreads();
    for (int s = 128; s > 0; s >>= 1) {
        if (tid < s) red[tid] += red[tid + s];
        __syncthreads();
    }
    float inv = 1.f / red[0];
    #pragma unroll
    for (int j = 0; j < 4; j++) row[tid + (j << 8)] = vals[j] * inv;
}

// ---------------- GEMM kernels ----------------
// C[M,N] = A[M,K] * B[N,K]^T   (both row-major, K contiguous)
// mode 0: store; mode 1: C = R + acc; mode 2: C = relu(acc)^2
// batched over blockIdx.z with element strides sA,sB,sC,sR.
__global__ void gemm_nt_k(const float* __restrict__ A, int lda, long long sA,
                          const float* __restrict__ B, int ldb, long long sB,
                          float* __restrict__ C, int ldc, long long sC,
                          const float* __restrict__ R, long long sR,
                          int K, int mode) {
    int bz = blockIdx.z;
    A += (size_t)bz * sA;
    B += (size_t)bz * sB;
    C += (size_t)bz * sC;
    if (R) R += (size_t)bz * sR;

    int row0 = blockIdx.y * 64;
    int col0 = blockIdx.x * 64;

    __shared__ float As[16][64];
    __shared__ float Bs[16][64];

    int tid = threadIdx.x;       // 256 threads
    int tx = tid & 15, ty = tid >> 4;
    int lr = tid >> 2;           // 0..63
    int lk = (tid & 3) << 2;     // 0,4,8,12

    float acc[4][4] = {};

    for (int k0 = 0; k0 < K; k0 += 16) {
        float4 a4 = *(const float4*)(A + (size_t)(row0 + lr) * lda + k0 + lk);
        float4 b4 = *(const float4*)(B + (size_t)(col0 + lr) * ldb + k0 + lk);
        As[lk + 0][lr] = a4.x; As[lk + 1][lr] = a4.y; As[lk + 2][lr] = a4.z; As[lk + 3][lr] = a4.w;
        Bs[lk + 0][lr] = b4.x; Bs[lk + 1][lr] = b4.y; Bs[lk + 2][lr] = b4.z; Bs[lk + 3][lr] = b4.w;
        __syncthreads();
        #pragma unroll
        for (int kk = 0; kk < 16; kk++) {
            float4 av = *(const float4*)&As[kk][ty << 2];
            float4 bv = *(const float4*)&Bs[kk][tx << 2];
            float a[4] = {av.x, av.y, av.z, av.w};
            float b[4] = {bv.x, bv.y, bv.z, bv.w};
            #pragma unroll
            for (int i = 0; i < 4; i++)
                #pragma unroll
                for (int j = 0; j < 4; j++)
                    acc[i][j] += a[i] * b[j];
        }
        __syncthreads();
    }

    #pragma unroll
    for (int i = 0; i < 4; i++) {
        int r = row0 + (ty << 2) + i;
        size_t off = (size_t)r * ldc + col0 + (tx << 2);
        float4 o;
        o.x = acc[i][0]; o.y = acc[i][1]; o.z = acc[i][2]; o.w = acc[i][3];
        if (mode == 1) {
            float4 rv = *(const float4*)(R + off);
            o.x += rv.x; o.y += rv.y; o.z += rv.z; o.w += rv.w;
        } else if (mode == 2) {
            o.x = fmaxf(o.x, 0.f); o.x *= o.x;
            o.y = fmaxf(o.y, 0.f); o.y *= o.y;
            o.z = fmaxf(o.z, 0.f); o.z *= o.z;
            o.w = fmaxf(o.w, 0.f); o.w *= o.w;
        }
        *(float4*)(C + off) = o;
    }
}

// C[M,N] = A[M,K] * B[K,N]   (normal-normal), batched over z
__global__ void gemm_nn_k(const float* __restrict__ A, int lda, long long sA,
                          const float* __restrict__ B, int ldb, long long sB,
                          float* __restrict__ C, int ldc, long long sC,
                          int K) {
    int bz = blockIdx.z;
    A += (size_t)bz * sA;
    B += (size_t)bz * sB;
    C += (size_t)bz * sC;

    int row0 = blockIdx.y * 64;
    int col0 = blockIdx.x * 64;

    __shared__ float As[16][64];
    __shared__ float Bs[16][64];

    int tid = threadIdx.x;
    int tx = tid & 15, ty = tid >> 4;
    int lr = tid >> 2;
    int lk = (tid & 3) << 2;
    int bk = tid >> 4;           // 0..15
    int bn = (tid & 15) << 2;    // 0..60

    float acc[4][4] = {};

    for (int k0 = 0; k0 < K; k0 += 16) {
        float4 a4 = *(const float4*)(A + (size_t)(row0 + lr) * lda + k0 + lk);
        As[lk + 0][lr] = a4.x; As[lk + 1][lr] = a4.y; As[lk + 2][lr] = a4.z; As[lk + 3][lr] = a4.w;
        *(float4*)&Bs[bk][bn] = *(const float4*)(B + (size_t)(k0 + bk) * ldb + col0 + bn);
        __syncthreads();
        #pragma unroll
        for (int kk = 0; kk < 16; kk++) {
            float4 av = *(const float4*)&As[kk][ty << 2];
            float4 bv = *(const float4*)&Bs[kk][tx << 2];
            float a[4] = {av.x, av.y, av.z, av.w};
            float b[4] = {bv.x, bv.y, bv.z, bv.w};
            #pragma unroll
            for (int i = 0; i < 4; i++)
                #pragma unroll
                for (int j = 0; j < 4; j++)
                    acc[i][j] += a[i] * b[j];
        }
        __syncthreads();
    }

    #pragma unroll
    for (int i = 0; i < 4; i++) {
        int r = row0 + (ty << 2) + i;
        size_t off = (size_t)r * ldc + col0 + (tx << 2);
        float4 o;
        o.x = acc[i][0]; o.y = acc[i][1]; o.z = acc[i][2]; o.w = acc[i][3];
        *(float4*)(C + off) = o;
    }
}

// ---------------- host orchestration ----------------

extern "C" void kernel_launch(void* const* d_in, const int* in_sizes, int n_in,
                              void* d_out, int out_size) {
    const float* x_in    = (const float*)d_in[0];
    const float* Wq      = (const float*)d_in[1];
    const float* Wk      = (const float*)d_in[2];
    const float* Wv      = (const float*)d_in[3];
    const float* Wo      = (const float*)d_in[4];
    const float* lamb    = (const float*)d_in[5];
    const float* lambdas = (const float*)d_in[6];
    const float* Wfc     = (const float*)d_in[7];
    const float* Wp      = (const float*)d_in[8];
    const int*   levels  = (const int*)d_in[9];
    const int*   sample  = (const int*)d_in[10];

    float *x, *x0, *xl, *xn, *q, *k, *v, *v1, *y, *h, *p;
    int* cpad;
    unsigned char* mask;
    cudaGetSymbolAddress((void**)&x,  g_x);
    cudaGetSymbolAddress((void**)&x0, g_x0);
    cudaGetSymbolAddress((void**)&xl, g_xl);
    cudaGetSymbolAddress((void**)&xn, g_xn);
    cudaGetSymbolAddress((void**)&q,  g_q);
    cudaGetSymbolAddress((void**)&k,  g_k);
    cudaGetSymbolAddress((void**)&v,  g_v);
    cudaGetSymbolAddress((void**)&v1, g_v1);
    cudaGetSymbolAddress((void**)&y,  g_y);
    cudaGetSymbolAddress((void**)&h,  g_h);
    cudaGetSymbolAddress((void**)&p,  g_p);
    cudaGetSymbolAddress((void**)&cpad, g_cpad);
    cudaGetSymbolAddress((void**)&mask, g_mask);

    const int EW = (S * D) / 256;           // elementwise grid
    const float scale = 1.0f / 8.0f;        // HD^-0.5 = 64^-0.5

    build_prefix_k<<<1, 32>>>(levels, cpad);
    build_mask_k<<<(S * S) / 256, 256>>>(levels, sample, cpad, mask);

    // x = rms(x_in); x0 = x
    rms_rows_k<<<S, 256>>>(x_in, x, D);
    copy_k<<<EW, 256>>>(x, x0);

    for (int i = 0; i < NL; i++) {
        const float* Wqi = Wq + (size_t)i * D * D;
        const float* Wki = Wk + (size_t)i * D * D;
        const float* Wvi = Wv + (size_t)i * D * D;
        const float* Woi = Wo + (size_t)i * D * D;
        const float* Wfi = Wfc + (size_t)i * DFF * D;
        const float* Wpi = Wp + (size_t)i * D * DFF;

        // xl = l0*x + l1*x0 ; xn = rms(xl)
        xl_k<<<EW, 256>>>(x, x0, lambdas, i, xl);
        rms_rows_k<<<S, 256>>>(xl, xn, D);

        // q,k,v projections: [S,D] @ [D,D]^T
        dim3 gproj(D / 64, S / 64, 1);
        gemm_nt_k<<<gproj, 256>>>(xn, D, 0, Wqi, D, 0, q, D, 0, nullptr, 0, D, 0);
        gemm_nt_k<<<gproj, 256>>>(xn, D, 0, Wki, D, 0, k, D, 0, nullptr, 0, D, 0);
        gemm_nt_k<<<gproj, 256>>>(xn, D, 0, Wvi, D, 0, v, D, 0, nullptr, 0, D, 0);

        if (i == 0) copy_k<<<EW, 256>>>(v, v1);
        vmix_k<<<EW, 256>>>(v, v1, lamb, i);

        // per-head rms + rope on q,k
        rms_head_k<<<(S * H * 32) / 256, 256>>>(q);
        rms_head_k<<<(S * H * 32) / 256, 256>>>(k);
        rope_k<<<(S * H * 32) / 256, 256>>>(q);
        rope_k<<<(S * H * 32) / 256, 256>>>(k);

        // scores[h] = q_h @ k_h^T   (batched over heads)
        dim3 gsc(S / 64, S / 64, H);
        gemm_nt_k<<<gsc, 256>>>(q, D, HD, k, D, HD, p, S, (long long)S * S,
                                nullptr, 0, HD, 0);

        // masked softmax (scale folded in)
        softmax_k<<<dim3(S, H), 256>>>(p, mask, scale);

        // y[:, h] = P_h @ V_h
        dim3 gpv(HD / 64, S / 64, H);
        gemm_nn_k<<<gpv, 256>>>(p, S, (long long)S * S, v, D, HD, y, D, HD, S);

        // x = xl + y @ Wo^T
        gemm_nt_k<<<gproj, 256>>>(y, D, 0, Woi, D, 0, x, D, 0, xl, 0, D, 1);

        // h = relu(rms(x) @ Wfc^T)^2
        rms_rows_k<<<S, 256>>>(x, xn, D);
        dim3 gfc(DFF / 64, S / 64, 1);
        gemm_nt_k<<<gfc, 256>>>(xn, D, 0, Wfi, D, 0, h, DFF, 0, nullptr, 0, D, 2);

        // x = x + h @ Wp^T
        gemm_nt_k<<<gproj, 256>>>(h, DFF, 0, Wpi, DFF, 0, x, D, 0, x, 0, DFF, 1);
    }

    // out = rms(x)
    rms_rows_k<<<S, 256>>>(x, (float*)d_out, D);
}

// round 2
// speedup vs baseline: 2.6878x; 2.6878x over previous
#include <cuda_runtime.h>
#include <math.h>
#include <stdint.h>

#define S 1024
#define D 1024
#define H 16
#define HD 64
#define NL 6
#define DFF 4096
#define EPS 1.1920929e-07f

// ---------------- scratch (device globals; no allocation) ----------------
__device__ float g_x [S * D];
__device__ float g_x0[S * D];
__device__ float g_xl[S * D];
__device__ float g_xn[S * D];
__device__ float g_q [S * D];
__device__ float g_k [S * D];
__device__ float g_v [S * D];
__device__ float g_v1[S * D];
__device__ float g_vt[S * D];
__device__ float g_y [S * D];
__device__ float g_h [S * DFF];
__device__ float g_p [(size_t)H * S * S];
__device__ int   g_cpad[S + 1];
__device__ unsigned char g_mask[(size_t)S * S];

// ---------------- helpers ----------------

__device__ __forceinline__ float tf32r(float x) {
    uint32_t u;
    asm("cvt.rna.tf32.f32 %0, %1;" : "=r"(u) : "f"(x));
    return __uint_as_float(u);
}

// ---------------- small kernels ----------------

__global__ void build_prefix_k(const int* __restrict__ levels, int* __restrict__ cpad) {
    if (threadIdx.x == 0) {
        cpad[0] = 0;
        for (int i = 0; i < S; i++) cpad[i + 1] = cpad[i] + (levels[i] == 0 ? 1 : 0);
    }
}

__global__ void build_mask_k(const int* __restrict__ levels, const int* __restrict__ sample,
                             const int* __restrict__ cpad, unsigned char* __restrict__ mask) {
    int idx = blockIdx.x * blockDim.x + threadIdx.x;
    int q = idx >> 10;
    int k = idx & 1023;
    bool causal = q >= k;
    bool same = sample[q] == sample[k];
    int cnt = cpad[q] - cpad[k + 1];
    bool markov = (levels[k] == 0) && (cnt > 0);
    mask[idx] = (causal && same && !markov) ? 1 : 0;
}

// RMS over rows of length L (L multiple of 1024 here; 256 threads)
__global__ void rms_rows_k(const float* __restrict__ in, float* __restrict__ out, int L) {
    int row = blockIdx.x;
    const float4* p = (const float4*)(in + (size_t)row * L);
    float4* o = (float4*)(out + (size_t)row * L);
    int tid = threadIdx.x;
    int L4 = L >> 2;
    float ss = 0.f;
    for (int i = tid; i < L4; i += 256) {
        float4 t = p[i];
        ss += t.x * t.x + t.y * t.y + t.z * t.z + t.w * t.w;
    }
    __shared__ float red[256];
    red[tid] = ss;
    __syncthreads();
    for (int s = 128; s > 0; s >>= 1) {
        if (tid < s) red[tid] += red[tid + s];
        __syncthreads();
    }
    float scale = rsqrtf(red[0] / (float)L + EPS);
    for (int i = tid; i < L4; i += 256) {
        float4 t = p[i];
        t.x *= scale; t.y *= scale; t.z *= scale; t.w *= scale;
        o[i] = t;
    }
}

// fused per-(s,h) RMS (64 elems) + RoPE; one warp per row
__global__ void rmsrope_k(float* __restrict__ t) {
    int warp = (blockIdx.x * blockDim.x + threadIdx.x) >> 5;
    int lane = threadIdx.x & 31;
    int s = warp >> 4;  // row index = s*H + h
    float* p = t + (size_t)warp * 64;
    float a = p[lane], b = p[lane + 32];
    float ss = a * a + b * b;
    #pragma unroll
    for (int o = 16; o; o >>= 1) ss += __shfl_xor_sync(0xFFFFFFFFu, ss, o);
    float sc = rsqrtf(ss / 64.f + EPS);
    a *= sc; b *= sc;
    float inv = powf(10000.f, -((float)(2 * lane)) / 64.f);
    float fr = (float)s * inv;
    float cs, sn;
    sincosf(fr, &sn, &cs);
    p[lane]      = a * cs + b * sn;
    p[lane + 32] = -a * sn + b * cs;
}

__global__ void copy4_k(const float4* __restrict__ in, float4* __restrict__ out) {
    int i = blockIdx.x * blockDim.x + threadIdx.x;
    out[i] = in[i];
}

__global__ void xl4_k(const float4* __restrict__ x, const float4* __restrict__ x0,
                      const float* __restrict__ lambdas, int layer, float4* __restrict__ xl) {
    int i = blockIdx.x * blockDim.x + threadIdx.x;
    float l0 = lambdas[layer * 2 + 0];
    float l1 = lambdas[layer * 2 + 1];
    float4 a = x[i], b = x0[i];
    xl[i] = make_float4(l0 * a.x + l1 * b.x, l0 * a.y + l1 * b.y,
                        l0 * a.z + l1 * b.z, l0 * a.w + l1 * b.w);
}

__global__ void vmix4_k(float4* __restrict__ v, const float4* __restrict__ v1,
                        const float* __restrict__ lamb, int layer) {
    int i = blockIdx.x * blockDim.x + threadIdx.x;
    float la = lamb[layer];
    float om = 1.f - la;
    float4 a = v[i], b = v1[i];
    v[i] = make_float4(om * a.x + la * b.x, om * a.y + la * b.y,
                       om * a.z + la * b.z, om * a.w + la * b.w);
}

// transpose 1024x1024: out[c][r] = in[r][c]
__global__ void transpose_k(const float* __restrict__ in, float* __restrict__ out) {
    __shared__ float tile[32][33];
    int x = blockIdx.x * 32 + threadIdx.x;
    int y0 = blockIdx.y * 32 + threadIdx.y;
    #pragma unroll
    for (int j = 0; j < 32; j += 8)
        tile[threadIdx.y + j][threadIdx.x] = in[(size_t)(y0 + j) * D + x];
    __syncthreads();
    int x2 = blockIdx.y * 32 + threadIdx.x;
    int y2 = blockIdx.x * 32 + threadIdx.y;
    #pragma unroll
    for (int j = 0; j < 32; j += 8)
        out[(size_t)(y2 + j) * D + x2] = tile[threadIdx.x][threadIdx.y + j];
}

// masked softmax over row of S, in-place on scores; scale folded in here
__global__ void softmax_k(float* __restrict__ p, const unsigned char* __restrict__ mask,
                          float scale) {
    int qi = blockIdx.x;
    int h = blockIdx.y;
    float* row = p + ((size_t)h * S + qi) * S;
    const unsigned char* m = mask + (size_t)qi * S;
    int tid = threadIdx.x;
    float vals[4];
    float mx = -1e30f;
    #pragma unroll
    for (int j = 0; j < 4; j++) {
        int k = tid + (j << 8);
        float v = m[k] ? row[k] * scale : -1e30f;
        vals[j] = v;
        mx = fmaxf(mx, v);
    }
    __shared__ float red[256];
    red[tid] = mx;
    __syncthreads();
    for (int s = 128; s > 0; s >>= 1) {
        if (tid < s) red[tid] = fmaxf(red[tid], red[tid + s]);
        __syncthreads();
    }
    mx = red[0];
    __syncthreads();
    float sum = 0.f;
    #pragma unroll
    for (int j = 0; j < 4; j++) { vals[j] = expf(vals[j] - mx); sum += vals[j]; }
    red[tid] = sum;
    __syncthreads();
    for (int s = 128; s > 0; s >>= 1) {
        if (tid < s) red[tid] += red[tid + s];
        __syncthreads();
    }
    float inv = 1.f / red[0];
    #pragma unroll
    for (int j = 0; j < 4; j++) row[tid + (j << 8)] = vals[j] * inv;
}

// ---------------- tf32 tensor-core GEMM ----------------
// C[M,N] = A[M,K] * B[N,K]^T  (NT; both row-major, K contiguous)
// mode 0: store; mode 1: C = R + acc; mode 2: C = relu(acc)^2
// batched over blockIdx.z; nMulti>0 selects B/C from pointer arrays (QKV fusion)

struct GemmArgs {
    const float* A; int lda; long long sA;
    const float* B; int ldb; long long sB;
    float* C; int ldc; long long sC;
    const float* R; long long sR;
    int K; int mode;
    const float* Bm[3]; float* Cm[3]; int nMulti;
};

template<int BM, int BN, int WM, int WN>
__global__ __launch_bounds__(256) void gemm_tf32(GemmArgs args) {
    constexpr int BK = 32;
    constexpr int WARPS_M = BM / WM;
    constexpr int FM = WM / 16, FN = WN / 8;
    constexpr int LA = BM / 32, LB = BN / 32;
    __shared__ __align__(16) float As[BM][BK + 4];
    __shared__ __align__(16) float Bs[BN][BK + 4];

    int z = blockIdx.z;
    const float* A = args.A + (size_t)z * args.sA;
    const float* B;
    float* C;
    if (args.nMulti) { B = args.Bm[z]; C = args.Cm[z]; }
    else { B = args.B + (size_t)z * args.sB; C = args.C + (size_t)z * args.sC; }
    const float* R = args.R;
    if (R) R += (size_t)z * args.sR;

    int row0 = blockIdx.y * BM, col0 = blockIdx.x * BN;
    int tid = threadIdx.x, lane = tid & 31, warp = tid >> 5;
    int wm0 = (warp % WARPS_M) * WM, wn0 = (warp / WARPS_M) * WN;
    int g = lane >> 2, tig = lane & 3;

    float acc[FM][FN][4];
    #pragma unroll
    for (int i = 0; i < FM; i++)
        #pragma unroll
        for (int j = 0; j < FN; j++)
            #pragma unroll
            for (int t = 0; t < 4; t++) acc[i][j][t] = 0.f;

    float4 ra[LA], rb[LB];
    int srow = tid >> 3, scol = (tid & 7) << 2;

    #pragma unroll
    for (int i = 0; i < LA; i++)
        ra[i] = *(const float4*)(A + (size_t)(row0 + srow + 32 * i) * args.lda + scol);
    #pragma unroll
    for (int i = 0; i < LB; i++)
        rb[i] = *(const float4*)(B + (size_t)(col0 + srow + 32 * i) * args.ldb + scol);

    int KT = args.K / BK;
    for (int kt = 0; kt < KT; kt++) {
        #pragma unroll
        for (int i = 0; i < LA; i++)
            *(float4*)&As[srow + 32 * i][scol] =
                make_float4(tf32r(ra[i].x), tf32r(ra[i].y), tf32r(ra[i].z), tf32r(ra[i].w));
        #pragma unroll
        for (int i = 0; i < LB; i++)
            *(float4*)&Bs[srow + 32 * i][scol] =
                make_float4(tf32r(rb[i].x), tf32r(rb[i].y), tf32r(rb[i].z), tf32r(rb[i].w));
        __syncthreads();

        if (kt + 1 < KT) {
            int k0 = (kt + 1) * BK + scol;
            #pragma unroll
            for (int i = 0; i < LA; i++)
                ra[i] = *(const float4*)(A + (size_t)(row0 + srow + 32 * i) * args.lda + k0);
            #pragma unroll
            for (int i = 0; i < LB; i++)
                rb[i] = *(const float4*)(B + (size_t)(col0 + srow + 32 * i) * args.ldb + k0);
        }

        #pragma unroll
        for (int k8 = 0; k8 < BK; k8 += 8) {
            uint32_t af[FM][4], bf[FN][2];
            #pragma unroll
            for (int fm = 0; fm < FM; fm++) {
                int r = wm0 + fm * 16 + g;
                af[fm][0] = __float_as_uint(As[r][k8 + tig]);
                af[fm][1] = __float_as_uint(As[r + 8][k8 + tig]);
                af[fm][2] = __float_as_uint(As[r][k8 + tig + 4]);
                af[fm][3] = __float_as_uint(As[r + 8][k8 + tig + 4]);
            }
            #pragma unroll
            for (int fn = 0; fn < FN; fn++) {
                int c = wn0 + fn * 8 + g;
                bf[fn][0] = __float_as_uint(Bs[c][k8 + tig]);
                bf[fn][1] = __float_as_uint(Bs[c][k8 + tig + 4]);
            }
            #pragma unroll
            for (int fm = 0; fm < FM; fm++)
                #pragma unroll
                for (int fn = 0; fn < FN; fn++) {
                    asm volatile(
                        "mma.sync.aligned.m16n8k8.row.col.f32.tf32.tf32.f32 "
                        "{%0,%1,%2,%3}, {%4,%5,%6,%7}, {%8,%9}, {%0,%1,%2,%3};\n"
                        : "+f"(acc[fm][fn][0]), "+f"(acc[fm][fn][1]),
                          "+f"(acc[fm][fn][2]), "+f"(acc[fm][fn][3])
                        : "r"(af[fm][0]), "r"(af[fm][1]), "r"(af[fm][2]), "r"(af[fm][3]),
                          "r"(bf[fn][0]), "r"(bf[fn][1]));
                }
        }
        __syncthreads();
    }

    // epilogue
    #pragma unroll
    for (int fm = 0; fm < FM; fm++) {
        #pragma unroll
        for (int fn = 0; fn < FN; fn++) {
            int r0 = row0 + wm0 + fm * 16 + g;
            int c  = col0 + wn0 + fn * 8 + 2 * tig;
            #pragma unroll
            for (int half = 0; half < 2; half++) {
                int r = r0 + 8 * half;
                float v0 = acc[fm][fn][2 * half + 0];
                float v1 = acc[fm][fn][2 * half + 1];
                size_t off = (size_t)r * args.ldc + c;
                if (args.mode == 1) {
                    v0 += R[off];
                    v1 += R[off + 1];
                } else if (args.mode == 2) {
                    v0 = fmaxf(v0, 0.f); v0 *= v0;
                    v1 = fmaxf(v1, 0.f); v1 *= v1;
                }
                C[off] = v0;
                C[off + 1] = v1;
            }
        }
    }
}

// ---------------- host orchestration ----------------

static inline GemmArgs mkargs(const float* A, int lda, long long sA,
                              const float* B, int ldb, long long sB,
                              float* C, int ldc, long long sC,
                              const float* R, long long sR, int K, int mode) {
    GemmArgs a;
    a.A = A; a.lda = lda; a.sA = sA;
    a.B = B; a.ldb = ldb; a.sB = sB;
    a.C = C; a.ldc = ldc; a.sC = sC;
    a.R = R; a.sR = sR; a.K = K; a.mode = mode;
    a.Bm[0] = a.Bm[1] = a.Bm[2] = nullptr;
    a.Cm[0] = a.Cm[1] = a.Cm[2] = nullptr;
    a.nMulti = 0;
    return a;
}

extern "C" void kernel_launch(void* const* d_in, const int* in_sizes, int n_in,
                              void* d_out, int out_size) {
    const float* x_in    = (const float*)d_in[0];
    const float* Wq      = (const float*)d_in[1];
    const float* Wk      = (const float*)d_in[2];
    const float* Wv      = (const float*)d_in[3];
    const float* Wo      = (const float*)d_in[4];
    const float* lamb    = (const float*)d_in[5];
    const float* lambdas = (const float*)d_in[6];
    const float* Wfc     = (const float*)d_in[7];
    const float* Wp      = (const float*)d_in[8];
    const int*   levels  = (const int*)d_in[9];
    const int*   sample  = (const int*)d_in[10];

    float *x, *x0, *xl, *xn, *q, *k, *v, *v1, *vt, *y, *h, *p;
    int* cpad;
    unsigned char* mask;
    cudaGetSymbolAddress((void**)&x,  g_x);
    cudaGetSymbolAddress((void**)&x0, g_x0);
    cudaGetSymbolAddress((void**)&xl, g_xl);
    cudaGetSymbolAddress((void**)&xn, g_xn);
    cudaGetSymbolAddress((void**)&q,  g_q);
    cudaGetSymbolAddress((void**)&k,  g_k);
    cudaGetSymbolAddress((void**)&v,  g_v);
    cudaGetSymbolAddress((void**)&v1, g_v1);
    cudaGetSymbolAddress((void**)&vt, g_vt);
    cudaGetSymbolAddress((void**)&y,  g_y);
    cudaGetSymbolAddress((void**)&h,  g_h);
    cudaGetSymbolAddress((void**)&p,  g_p);
    cudaGetSymbolAddress((void**)&cpad, g_cpad);
    cudaGetSymbolAddress((void**)&mask, g_mask);

    const int EW4 = (S * D / 4) / 256;
    const float scale = 1.0f / 8.0f;  // HD^-0.5

    build_prefix_k<<<1, 32>>>(levels, cpad);
    build_mask_k<<<(S * S) / 256, 256>>>(levels, sample, cpad, mask);

    rms_rows_k<<<S, 256>>>(x_in, x, D);
    copy4_k<<<EW4, 256>>>((const float4*)x, (float4*)x0);

    for (int i = 0; i < NL; i++) {
        const float* Wqi = Wq + (size_t)i * D * D;
        const float* Wki = Wk + (size_t)i * D * D;
        const float* Wvi = Wv + (size_t)i * D * D;
        const float* Woi = Wo + (size_t)i * D * D;
        const float* Wfi = Wfc + (size_t)i * DFF * D;
        const float* Wpi = Wp + (size_t)i * D * DFF;

        // xl = l0*x + l1*x0 ; xn = rms(xl)
        xl4_k<<<EW4, 256>>>((const float4*)x, (const float4*)x0, lambdas, i, (float4*)xl);
        rms_rows_k<<<S, 256>>>(xl, xn, D);

        // fused QKV: z in {0,1,2} selects weight + output
        {
            GemmArgs a = mkargs(xn, D, 0, nullptr, D, 0, nullptr, D, 0, nullptr, 0, D, 0);
            a.Bm[0] = Wqi; a.Bm[1] = Wki; a.Bm[2] = Wvi;
            a.Cm[0] = q;   a.Cm[1] = k;   a.Cm[2] = v;
            a.nMulti = 3;
            gemm_tf32<128, 128, 64, 32><<<dim3(D / 128, S / 128, 3), 256>>>(a);
        }

        if (i == 0) copy4_k<<<EW4, 256>>>((const float4*)v, (float4*)v1);
        vmix4_k<<<EW4, 256>>>((float4*)v, (const float4*)v1, lamb, i);

        // per-head rms + rope on q,k (fused)
        rmsrope_k<<<(S * H) / 8, 256>>>(q);
        rmsrope_k<<<(S * H) / 8, 256>>>(k);

        // vt = v^T  (so PV becomes NT gemm)
        transpose_k<<<dim3(32, 32), dim3(32, 8)>>>(v, vt);

        // scores[h] = q_h @ k_h^T
        {
            GemmArgs a = mkargs(q, D, HD, k, D, HD, p, S, (long long)S * S, nullptr, 0, HD, 0);
            gemm_tf32<128, 128, 64, 32><<<dim3(S / 128, S / 128, H), 256>>>(a);
        }

        softmax_k<<<dim3(S, H), 256>>>(p, mask, scale);

        // y[:, h] = P_h @ V_h  (NT against vt)
        {
            GemmArgs a = mkargs(p, S, (long long)S * S, vt, D, (long long)HD * D,
                                y, D, HD, nullptr, 0, S, 0);
            gemm_tf32<128, 64, 32, 32><<<dim3(1, S / 128, H), 256>>>(a);
        }

        // x = xl + y @ Wo^T
        {
            GemmArgs a = mkargs(y, D, 0, Woi, D, 0, x, D, 0, xl, 0, D, 1);
            gemm_tf32<64, 128, 32, 32><<<dim3(D / 128, S / 64, 1), 256>>>(a);
        }

        // h = relu(rms(x) @ Wfc^T)^2
        rms_rows_k<<<S, 256>>>(x, xn, D);
        {
            GemmArgs a = mkargs(xn, D, 0, Wfi, D, 0, h, DFF, 0, nullptr, 0, D, 2);
            gemm_tf32<128, 128, 64, 32><<<dim3(DFF / 128, S / 128, 1), 256>>>(a);
        }

        // x = x + h @ Wp^T
        {
            GemmArgs a = mkargs(h, DFF, 0, Wpi, DFF, 0, x, D, 0, x, 0, DFF, 1);
            gemm_tf32<64, 128, 32, 32><<<dim3(D / 128, S / 64, 1), 256>>>(a);
        }
    }

    rms_rows_k<<<S, 256>>>(x, (float*)d_out, D);
}

// round 3
// speedup vs baseline: 3.4607x; 1.2875x over previous
#include <cuda_runtime.h>
#include <math.h>
#include <stdint.h>

#define S 1024
#define D 1024
#define H 16
#define HD 64
#define NL 6
#define DFF 4096
#define EPS 1.1920929e-07f

// ---------------- scratch (device globals; no allocation) ----------------
__device__ float g_x [S * D];
__device__ float g_x0[S * D];
__device__ float g_xl[S * D];
__device__ float g_xn[S * D];
__device__ float g_q [S * D];
__device__ float g_k [S * D];
__device__ float g_v [S * D];
__device__ float g_v1[S * D];
__device__ float g_vt[S * D];
__device__ float g_y [S * D];
__device__ float g_h [S * DFF];
__device__ float g_p [(size_t)H * S * S];
__device__ float g_rs[(size_t)H * S];
__device__ int   g_cpad[S + 1];
__device__ unsigned char g_mask[(size_t)S * S];

// ---------------- helpers ----------------

__device__ __forceinline__ float tf32r(float x) {
    uint32_t u;
    asm("cvt.rna.tf32.f32 %0, %1;" : "=r"(u) : "f"(x));
    return __uint_as_float(u);
}

// ---------------- small kernels ----------------

__global__ void build_prefix_k(const int* __restrict__ levels, int* __restrict__ cpad) {
    if (threadIdx.x == 0) {
        cpad[0] = 0;
        for (int i = 0; i < S; i++) cpad[i + 1] = cpad[i] + (levels[i] == 0 ? 1 : 0);
    }
}

__global__ void build_mask_k(const int* __restrict__ levels, const int* __restrict__ sample,
                             const int* __restrict__ cpad, unsigned char* __restrict__ mask) {
    int idx = blockIdx.x * blockDim.x + threadIdx.x;
    int q = idx >> 10;
    int k = idx & 1023;
    bool causal = q >= k;
    bool same = sample[q] == sample[k];
    int cnt = cpad[q] - cpad[k + 1];
    bool markov = (levels[k] == 0) && (cnt > 0);
    mask[idx] = (causal && same && !markov) ? 1 : 0;
}

// RMS over rows of length L; optional tf32 rounding of output
__global__ void rms_rows_k(const float* __restrict__ in, float* __restrict__ out, int L, int cvt) {
    int row = blockIdx.x;
    const float4* p = (const float4*)(in + (size_t)row * L);
    float4* o = (float4*)(out + (size_t)row * L);
    int tid = threadIdx.x;
    int L4 = L >> 2;
    float ss = 0.f;
    for (int i = tid; i < L4; i += 256) {
        float4 t = p[i];
        ss += t.x * t.x + t.y * t.y + t.z * t.z + t.w * t.w;
    }
    __shared__ float red[256];
    red[tid] = ss;
    __syncthreads();
    for (int s = 128; s > 0; s >>= 1) {
        if (tid < s) red[tid] += red[tid + s];
        __syncthreads();
    }
    float scale = rsqrtf(red[0] / (float)L + EPS);
    for (int i = tid; i < L4; i += 256) {
        float4 t = p[i];
        t.x *= scale; t.y *= scale; t.z *= scale; t.w *= scale;
        if (cvt) { t.x = tf32r(t.x); t.y = tf32r(t.y); t.z = tf32r(t.z); t.w = tf32r(t.w); }
        o[i] = t;
    }
}

// fused per-(s,h) RMS (64 elems) + RoPE; one warp per row; outputs tf32-rounded
__global__ void rmsrope_k(float* __restrict__ t) {
    int warp = (blockIdx.x * blockDim.x + threadIdx.x) >> 5;
    int lane = threadIdx.x & 31;
    int s = warp >> 4;
    float* p = t + (size_t)warp * 64;
    float a = p[lane], b = p[lane + 32];
    float ss = a * a + b * b;
    #pragma unroll
    for (int o = 16; o; o >>= 1) ss += __shfl_xor_sync(0xFFFFFFFFu, ss, o);
    float sc = rsqrtf(ss / 64.f + EPS);
    a *= sc; b *= sc;
    float inv = powf(10000.f, -((float)(2 * lane)) / 64.f);
    float fr = (float)s * inv;
    float cs, sn;
    sincosf(fr, &sn, &cs);
    p[lane]      = tf32r(a * cs + b * sn);
    p[lane + 32] = tf32r(-a * sn + b * cs);
}

__global__ void copy4_k(const float4* __restrict__ in, float4* __restrict__ out) {
    int i = blockIdx.x * blockDim.x + threadIdx.x;
    out[i] = in[i];
}

__global__ void xl4_k(const float4* __restrict__ x, const float4* __restrict__ x0,
                      const float* __restrict__ lambdas, int layer, float4* __restrict__ xl) {
    int i = blockIdx.x * blockDim.x + threadIdx.x;
    float l0 = lambdas[layer * 2 + 0];
    float l1 = lambdas[layer * 2 + 1];
    float4 a = x[i], b = x0[i];
    xl[i] = make_float4(l0 * a.x + l1 * b.x, l0 * a.y + l1 * b.y,
                        l0 * a.z + l1 * b.z, l0 * a.w + l1 * b.w);
}

__global__ void vmix4_k(float4* __restrict__ v, const float4* __restrict__ v1,
                        const float* __restrict__ lamb, int layer) {
    int i = blockIdx.x * blockDim.x + threadIdx.x;
    float la = lamb[layer];
    float om = 1.f - la;
    float4 a = v[i], b = v1[i];
    v[i] = make_float4(om * a.x + la * b.x, om * a.y + la * b.y,
                       om * a.z + la * b.z, om * a.w + la * b.w);
}

// transpose 1024x1024 with tf32 rounding: out[c][r] = tf32(in[r][c])
__global__ void transpose_k(const float* __restrict__ in, float* __restrict__ out) {
    __shared__ float tile[32][33];
    int x = blockIdx.x * 32 + threadIdx.x;
    int y0 = blockIdx.y * 32 + threadIdx.y;
    #pragma unroll
    for (int j = 0; j < 32; j += 8)
        tile[threadIdx.y + j][threadIdx.x] = in[(size_t)(y0 + j) * D + x];
    __syncthreads();
    int x2 = blockIdx.y * 32 + threadIdx.x;
    int y2 = blockIdx.x * 32 + threadIdx.y;
    #pragma unroll
    for (int j = 0; j < 32; j += 8)
        out[(size_t)(y2 + j) * D + x2] = tf32r(tile[threadIdx.x][threadIdx.y + j]);
}

// row sums of exp-scores: rs[h*S+q] = 1 / sum_k p[h][q][k]
// valid (computed) region of each row is k < ((q>>7)+1)<<7 ; beyond q it is 0.
__global__ void rowsum_k(const float* __restrict__ p, float* __restrict__ rs) {
    int row = blockIdx.x * 8 + (threadIdx.x >> 5);   // h*S + q
    int lane = threadIdx.x & 31;
    int q = row & (S - 1);
    const float4* pr = (const float4*)(p + (size_t)row * S);
    int n4 = (((q >> 7) + 1) << 7) >> 2;
    float s = 0.f;
    for (int i = lane; i < n4; i += 32) {
        float4 t = pr[i];
        s += t.x + t.y + t.z + t.w;
    }
    #pragma unroll
    for (int o = 16; o; o >>= 1) s += __shfl_xor_sync(0xFFFFFFFFu, s, o);
    if (lane == 0) rs[row] = 1.f / s;
}

// ---------------- pipelined tf32 tensor-core GEMM ----------------
// C[M,N] = A[M,K] * B[N,K]^T  (NT; row-major, K contiguous)
// modes: 0 store raw | 1 C=acc+R | 2 C=tf32(relu(acc)^2) | 3 C=mask?tf32(exp(acc*scale)):0
//        4 C=tf32(acc*R[row])  (R = per-row scale vector)
// flags: bit0 = lower-triangular launch (z encodes head+block), bit1 = K limited to row0+BM

struct GArgs {
    const float* A; int lda; long long sA;
    const float* B; int ldb; long long sB;
    float* C; int ldc; long long sC;
    const float* R; long long sR;
    int K; int mode; int flags; float scale;
    const unsigned char* mask;
    const float* Bm[3]; float* Cm[3]; int nMulti;
};

template<int BM, int BN, int WM, int WN, bool CVTB>
__global__ __launch_bounds__(256, 2) void gemm2(GArgs a) {
    constexpr int BK = 32;
    constexpr int SROW = 36;                 // padded row (floats); 144B, 16B-aligned
    constexpr int SSZ = (BM + BN) * SROW;    // floats per stage
    constexpr int WARPS_M = BM / WM;
    constexpr int FM = WM / 16, FN = WN / 8;
    constexpr int CA = BM / 32, CB = BN / 32;  // cp.async chunks per thread
    extern __shared__ float sh[];

    int tid = threadIdx.x, lane = tid & 31, warp = tid >> 5;
    int row0, col0;
    const float *A, *B;
    float* C;
    const float* R = nullptr;

    if (a.flags & 1) {
        int t = blockIdx.z % 36, h = blockIdx.z / 36;
        int by = 0;
        while ((by + 1) * (by + 2) / 2 <= t) by++;
        int bx = t - by * (by + 1) / 2;
        row0 = by * BM; col0 = bx * BN;
        A = a.A + (size_t)h * a.sA;
        B = a.B + (size_t)h * a.sB;
        C = a.C + (size_t)h * a.sC;
    } else {
        int z = blockIdx.z;
        row0 = blockIdx.y * BM; col0 = blockIdx.x * BN;
        if (a.nMulti) { A = a.A; B = a.Bm[z]; C = a.Cm[z]; }
        else { A = a.A + (size_t)z * a.sA; B = a.B + (size_t)z * a.sB; C = a.C + (size_t)z * a.sC; }
        if (a.R) R = a.R + (size_t)z * a.sR;
    }

    int K = a.K;
    if (a.flags & 2) { int kl = row0 + BM; if (kl < K) K = kl; }
    int KT = K / BK;

    auto issue = [&](int kt, int st) {
        float* dstA = sh + st * SSZ;
        #pragma unroll
        for (int i = 0; i < CA; i++) {
            int id = tid + 256 * i;
            int r = id >> 3, c = id & 7;
            unsigned u = (unsigned)__cvta_generic_to_shared(dstA + r * SROW + c * 4);
            const float* gp = A + (size_t)(row0 + r) * a.lda + kt * BK + c * 4;
            asm volatile("cp.async.cg.shared.global [%0], [%1], 16;\n" :: "r"(u), "l"(gp));
        }
        float* dstB = sh + st * SSZ + BM * SROW;
        #pragma unroll
        for (int i = 0; i < CB; i++) {
            int id = tid + 256 * i;
            int r = id >> 3, c = id & 7;
            unsigned u = (unsigned)__cvta_generic_to_shared(dstB + r * SROW + c * 4);
            const float* gp = B + (size_t)(col0 + r) * a.ldb + kt * BK + c * 4;
            asm volatile("cp.async.cg.shared.global [%0], [%1], 16;\n" :: "r"(u), "l"(gp));
        }
        asm volatile("cp.async.commit_group;\n");
    };

    float acc[FM][FN][4] = {};

    issue(0, 0);
    if (KT > 1) issue(1, 1);

    int wm0 = (warp % WARPS_M) * WM, wn0 = (warp / WARPS_M) * WN;
    int g = lane >> 2, tig = lane & 3;

    for (int kt = 0; kt < KT; kt++) {
        if (kt + 2 <= KT) asm volatile("cp.async.wait_group 1;\n");
        else              asm volatile("cp.async.wait_group 0;\n");
        __syncthreads();

        const float* As = sh + (kt & 1) * SSZ;
        const float* Bs = As + BM * SROW;

        #pragma unroll
        for (int k8 = 0; k8 < BK; k8 += 8) {
            uint32_t af[FM][4], bf[FN][2];
            #pragma unroll
            for (int fm = 0; fm < FM; fm++) {
                int r = wm0 + fm * 16 + g;
                af[fm][0] = __float_as_uint(As[r * SROW + k8 + tig]);
                af[fm][1] = __float_as_uint(As[(r + 8) * SROW + k8 + tig]);
                af[fm][2] = __float_as_uint(As[r * SROW + k8 + tig + 4]);
                af[fm][3] = __float_as_uint(As[(r + 8) * SROW + k8 + tig + 4]);
            }
            #pragma unroll
            for (int fn = 0; fn < FN; fn++) {
                int c = wn0 + fn * 8 + g;
                float b0 = Bs[c * SROW + k8 + tig];
                float b1 = Bs[c * SROW + k8 + tig + 4];
                if (CVTB) { b0 = tf32r(b0); b1 = tf32r(b1); }
                bf[fn][0] = __float_as_uint(b0);
                bf[fn][1] = __float_as_uint(b1);
            }
            #pragma unroll
            for (int fm = 0; fm < FM; fm++)
                #pragma unroll
                for (int fn = 0; fn < FN; fn++) {
                    asm volatile(
                        "mma.sync.aligned.m16n8k8.row.col.f32.tf32.tf32.f32 "
                        "{%0,%1,%2,%3}, {%4,%5,%6,%7}, {%8,%9}, {%0,%1,%2,%3};\n"
                        : "+f"(acc[fm][fn][0]), "+f"(acc[fm][fn][1]),
                          "+f"(acc[fm][fn][2]), "+f"(acc[fm][fn][3])
                        : "r"(af[fm][0]), "r"(af[fm][1]), "r"(af[fm][2]), "r"(af[fm][3]),
                          "r"(bf[fn][0]), "r"(bf[fn][1]));
                }
        }
        __syncthreads();
        if (kt + 2 < KT) issue(kt + 2, kt & 1);
    }

    // epilogue
    #pragma unroll
    for (int fm = 0; fm < FM; fm++) {
        #pragma unroll
        for (int fn = 0; fn < FN; fn++) {
            int r0 = row0 + wm0 + fm * 16 + g;
            int c  = col0 + wn0 + fn * 8 + 2 * tig;
            #pragma unroll
            for (int half = 0; half < 2; half++) {
                int r = r0 + 8 * half;
                float v0 = acc[fm][fn][2 * half + 0];
                float v1 = acc[fm][fn][2 * half + 1];
                size_t off = (size_t)r * a.ldc + c;
                if (a.mode == 1) {
                    v0 += R[off];
                    v1 += R[off + 1];
                } else if (a.mode == 2) {
                    v0 = fmaxf(v0, 0.f); v0 = tf32r(v0 * v0);
                    v1 = fmaxf(v1, 0.f); v1 = tf32r(v1 * v1);
                } else if (a.mode == 3) {
                    const unsigned char* m = a.mask + (size_t)r * S + c;
                    v0 = m[0] ? tf32r(__expf(v0 * a.scale)) : 0.f;
                    v1 = m[1] ? tf32r(__expf(v1 * a.scale)) : 0.f;
                } else if (a.mode == 4) {
                    float rsv = R[r];
                    v0 = tf32r(v0 * rsv);
                    v1 = tf32r(v1 * rsv);
                }
                C[off] = v0;
                C[off + 1] = v1;
            }
        }
    }
}

// ---------------- host orchestration ----------------

static inline GArgs mkargs(const float* A, int lda, long long sA,
                           const float* B, int ldb, long long sB,
                           float* C, int ldc, long long sC,
                           const float* R, long long sR, int K, int mode) {
    GArgs a;
    a.A = A; a.lda = lda; a.sA = sA;
    a.B = B; a.ldb = ldb; a.sB = sB;
    a.C = C; a.ldc = ldc; a.sC = sC;
    a.R = R; a.sR = sR; a.K = K; a.mode = mode;
    a.flags = 0; a.scale = 0.f; a.mask = nullptr;
    a.Bm[0] = a.Bm[1] = a.Bm[2] = nullptr;
    a.Cm[0] = a.Cm[1] = a.Cm[2] = nullptr;
    a.nMulti = 0;
    return a;
}

extern "C" void kernel_launch(void* const* d_in, const int* in_sizes, int n_in,
                              void* d_out, int out_size) {
    const float* x_in    = (const float*)d_in[0];
    const float* Wq      = (const float*)d_in[1];
    const float* Wk      = (const float*)d_in[2];
    const float* Wv      = (const float*)d_in[3];
    const float* Wo      = (const float*)d_in[4];
    const float* lamb    = (const float*)d_in[5];
    const float* lambdas = (const float*)d_in[6];
    const float* Wfc     = (const float*)d_in[7];
    const float* Wp      = (const float*)d_in[8];
    const int*   levels  = (const int*)d_in[9];
    const int*   sample  = (const int*)d_in[10];

    float *x, *x0, *xl, *xn, *q, *k, *v, *v1, *vt, *y, *h, *p, *rs;
    int* cpad;
    unsigned char* mask;
    cudaGetSymbolAddress((void**)&x,  g_x);
    cudaGetSymbolAddress((void**)&x0, g_x0);
    cudaGetSymbolAddress((void**)&xl, g_xl);
    cudaGetSymbolAddress((void**)&xn, g_xn);
    cudaGetSymbolAddress((void**)&q,  g_q);
    cudaGetSymbolAddress((void**)&k,  g_k);
    cudaGetSymbolAddress((void**)&v,  g_v);
    cudaGetSymbolAddress((void**)&v1, g_v1);
    cudaGetSymbolAddress((void**)&vt, g_vt);
    cudaGetSymbolAddress((void**)&y,  g_y);
    cudaGetSymbolAddress((void**)&h,  g_h);
    cudaGetSymbolAddress((void**)&p,  g_p);
    cudaGetSymbolAddress((void**)&rs, g_rs);
    cudaGetSymbolAddress((void**)&cpad, g_cpad);
    cudaGetSymbolAddress((void**)&mask, g_mask);

    // dynamic smem sizes per config (2 stages, padded rows)
    const int SM_A = (128 + 128) * 36 * 2 * 4;  // 73728
    const int SM_B = (64 + 128) * 36 * 2 * 4;   // 55296
    const int SM_C = (128 + 64) * 36 * 2 * 4;   // 55296
    cudaFuncSetAttribute(gemm2<128,128,64,32,true >, cudaFuncAttributeMaxDynamicSharedMemorySize, SM_A);
    cudaFuncSetAttribute(gemm2<128,128,64,32,false>, cudaFuncAttributeMaxDynamicSharedMemorySize, SM_A);
    cudaFuncSetAttribute(gemm2<64,128,32,32,true  >, cudaFuncAttributeMaxDynamicSharedMemorySize, SM_B);
    cudaFuncSetAttribute(gemm2<128,64,32,32,false >, cudaFuncAttributeMaxDynamicSharedMemorySize, SM_C);

    const int EW4 = (S * D / 4) / 256;
    const float scale = 1.0f / 8.0f;  // HD^-0.5

    build_prefix_k<<<1, 32>>>(levels, cpad);
    build_mask_k<<<(S * S) / 256, 256>>>(levels, sample, cpad, mask);

    rms_rows_k<<<S, 256>>>(x_in, x, D, 0);
    copy4_k<<<EW4, 256>>>((const float4*)x, (float4*)x0);

    for (int i = 0; i < NL; i++) {
        const float* Wqi = Wq + (size_t)i * D * D;
        const float* Wki = Wk + (size_t)i * D * D;
        const float* Wvi = Wv + (size_t)i * D * D;
        const float* Woi = Wo + (size_t)i * D * D;
        const float* Wfi = Wfc + (size_t)i * DFF * D;
        const float* Wpi = Wp + (size_t)i * D * DFF;

        // xl = l0*x + l1*x0 ; xn = tf32(rms(xl))
        xl4_k<<<EW4, 256>>>((const float4*)x, (const float4*)x0, lambdas, i, (float4*)xl);
        rms_rows_k<<<S, 256>>>(xl, xn, D, 1);

        // fused QKV
        {
            GArgs a = mkargs(xn, D, 0, nullptr, D, 0, nullptr, D, 0, nullptr, 0, D, 0);
            a.Bm[0] = Wqi; a.Bm[1] = Wki; a.Bm[2] = Wvi;
            a.Cm[0] = q;   a.Cm[1] = k;   a.Cm[2] = v;
            a.nMulti = 3;
            gemm2<128,128,64,32,true><<<dim3(D/128, S/128, 3), 256, SM_A>>>(a);
        }

        if (i == 0) copy4_k<<<EW4, 256>>>((const float4*)v, (float4*)v1);
        vmix4_k<<<EW4, 256>>>((float4*)v, (const float4*)v1, lamb, i);

        rmsrope_k<<<(S * H) / 8, 256>>>(q);
        rmsrope_k<<<(S * H) / 8, 256>>>(k);

        // vt = tf32(v^T)
        transpose_k<<<dim3(32, 32), dim3(32, 8)>>>(v, vt);

        // p[h] = mask .* exp(scale * q_h k_h^T), lower-triangular blocks only
        {
            GArgs a = mkargs(q, D, HD, k, D, HD, p, S, (long long)S * S, nullptr, 0, HD, 3);
            a.flags = 1; a.scale = scale; a.mask = mask;
            gemm2<128,128,64,32,false><<<dim3(1, 1, H * 36), 256, SM_A>>>(a);
        }

        // rs = 1 / rowsum(p)
        rowsum_k<<<(H * S) / 8, 256>>>(p, rs);

        // y[:,h] = tf32( (p_h @ V_h) * rs )   with K limited to row0+128
        {
            GArgs a = mkargs(p, S, (long long)S * S, vt, S, (long long)HD * S,
                             y, D, HD, rs, S, S, 4);
            a.flags = 2;
            gemm2<128,64,32,32,false><<<dim3(1, S/128, H), 256, SM_C>>>(a);
        }

        // x = xl + y @ Wo^T
        {
            GArgs a = mkargs(y, D, 0, Woi, D, 0, x, D, 0, xl, 0, D, 1);
            gemm2<64,128,32,32,true><<<dim3(D/128, S/64, 1), 256, SM_B>>>(a);
        }

        // h = tf32(relu(rms(x) @ Wfc^T)^2)
        rms_rows_k<<<S, 256>>>(x, xn, D, 1);
        {
            GArgs a = mkargs(xn, D, 0, Wfi, D, 0, h, DFF, 0, nullptr, 0, D, 2);
            gemm2<128,128,64,32,true><<<dim3(DFF/128, S/128, 1), 256, SM_A>>>(a);
        }

        // x = x + h @ Wp^T
        {
            GArgs a = mkargs(h, DFF, 0, Wpi, DFF, 0, x, D, 0, x, 0, DFF, 1);
            gemm2<64,128,32,32,true><<<dim3(D/128, S/64, 1), 256, SM_B>>>(a);
        }
    }

    rms_rows_k<<<S, 256>>>(x, (float*)d_out, D, 0);
}